// round 6
// baseline (speedup 1.0000x reference)
#include <cuda_runtime.h>

#define DT 0.01f

constexpr int B    = 2;
constexpr int N    = 20000;
constexpr int D    = 64;
constexpr int E    = 320000;
constexpr int ND   = N * D;          // floats per batch       = 1,280,000
constexpr int ND2  = ND / 2;         // float2s per batch      = 640,000
constexpr int TOT2 = B * ND2;        // float2s per (B,N,D)    = 1,280,000
constexpr int CAP  = 128;            // max supported in-degree (Poisson(16) tail << CAP)

// Scratch (allocation-free rule: __device__ globals, zero-initialized at load).
__device__ int g_cursor[N];          // per-node in-degree / write cursor
__device__ int g_bucket[N * CAP];    // src lists grouped by dst

// ---------------------------------------------------------------------------
// K1: bucket edges by dst.  pos = cursor[dst]++ ; bucket[dst][pos] = src
// ---------------------------------------------------------------------------
__global__ void bucket_kernel(const int2* __restrict__ edges) {
    int e = blockIdx.x * blockDim.x + threadIdx.x;
    if (e >= E) return;
    int2 ed = __ldg(&edges[e]);
    int pos = atomicAdd(&g_cursor[ed.y], 1);
    if (pos < CAP) g_bucket[ed.y * CAP + pos] = ed.x;
}

// ---------------------------------------------------------------------------
// K2: one warp per node.  Register-private segment sum of q[src] with
// compile-time-batched gathers (unroll-8, unconditional loads, predicated
// adds) for high MLP, then fused symplectic + Kalman epilogue.
// Resets cursor[n] = 0 for the next graph replay.
// ---------------------------------------------------------------------------
__global__ void __launch_bounds__(256) node_kernel(
        const float* __restrict__ q, const float* __restrict__ p,
        const float* __restrict__ obs, const float* __restrict__ kg,
        float* __restrict__ out) {
    int n = blockIdx.x * (blockDim.x >> 5) + (threadIdx.x >> 5);
    if (n >= N) return;
    int lane = threadIdx.x & 31;

    // Issue both scoreboarded loads back-to-back (independent): bucket row
    // contents never depend on the cursor value — stale tail entries are
    // excluded by the predicated adds below.
    int my_src0 = g_bucket[n * CAP + lane];   // first 32 srcs (may include stale tail)
    int deg     = g_cursor[n];                // broadcast load
    if (lane == 0) g_cursor[n] = 0;           // reset for next replay (after read)

    const float2* q2 = reinterpret_cast<const float2*>(q);
    const float2* p2 = reinterpret_cast<const float2*>(p);

    // Each lane owns dims [2*lane, 2*lane+1].  Accumulate sum of q[src].
    float2 a0 = make_float2(0.f, 0.f);   // batch 0
    float2 a1 = make_float2(0.f, 0.f);   // batch 1

    int degc = min(deg, CAP);
    for (int chunk = 0; chunk * 32 < degc; chunk++) {
        int ms  = (chunk == 0) ? my_src0
                               : g_bucket[n * CAP + chunk * 32 + lane];
        int lim = min(degc - chunk * 32, 32);
        for (int b = 0; b < lim; b += 8) {
            // 8 shfls + 16 unconditional LDG.64s batch together (MLP ~16);
            // adds are predicated on validity.
            #pragma unroll
            for (int j = 0; j < 8; j++) {
                int src = __shfl_sync(0xffffffffu, ms, b + j);
                float2 v0 = __ldg(&q2[src * 32 + lane]);
                float2 v1 = __ldg(&q2[ND2 + src * 32 + lane]);
                if (b + j < lim) {
                    a0.x += v0.x;  a0.y += v0.y;
                    a1.x += v1.x;  a1.y += v1.y;
                }
            }
        }
    }

    float dg = (float)deg;
    float2 qq0 = q2[n * 32 + lane];
    float2 pp0 = p2[n * 32 + lane];
    float2 qq1 = q2[ND2 + n * 32 + lane];
    float2 pp1 = p2[ND2 + n * 32 + lane];

    // msg = deg * q[n] - sum(q[src])
    float m0x = dg * qq0.x - a0.x,  m0y = dg * qq0.y - a0.y;
    float m1x = dg * qq1.x - a1.x,  m1y = dg * qq1.y - a1.y;

    // p_half = p + 0.5*DT*msg ; q_new = q + DT*p_half ; p_new = p + DT*msg
    float qn0x = qq0.x + DT * (pp0.x + 0.5f * DT * m0x);
    float qn0y = qq0.y + DT * (pp0.y + 0.5f * DT * m0y);
    float qn1x = qq1.x + DT * (pp1.x + 0.5f * DT * m1x);
    float qn1y = qq1.y + DT * (pp1.y + 0.5f * DT * m1y);

    float pn0x = pp0.x + DT * m0x,  pn0y = pp0.y + DT * m0y;
    float pn1x = pp1.x + DT * m1x,  pn1y = pp1.y + DT * m1y;

    if (n == 0) {
        const float2* obs2 = reinterpret_cast<const float2*>(obs);
        const float2* kg2  = reinterpret_cast<const float2*>(kg);
        float2 kq = kg2[lane];           // kalman_gain[0:D]
        float2 kp = kg2[32 + lane];      // kalman_gain[D:2D]
        float2 ob0 = obs2[lane];         // observations[0]
        float2 ob1 = obs2[32 + lane];    // observations[1]

        float i0x = ob0.x - qn0x, i0y = ob0.y - qn0y;
        float i1x = ob1.x - qn1x, i1y = ob1.y - qn1y;
        qn0x += kq.x * i0x;  qn0y += kq.y * i0y;
        qn1x += kq.x * i1x;  qn1y += kq.y * i1y;
        pn0x += kp.x * i0x;  pn0y += kp.y * i0y;
        pn1x += kp.x * i1x;  pn1y += kp.y * i1y;
    }

    float2* o2 = reinterpret_cast<float2*>(out);
    int idx0 = n * 32 + lane;            // batch 0 node offset (float2 units)
    // q_new: (B,N,D) at [0, TOT2) ; p_new: (B,N,D) at [TOT2, 2*TOT2)
    o2[idx0]               = make_float2(qn0x, qn0y);
    o2[ND2 + idx0]         = make_float2(qn1x, qn1y);
    o2[TOT2 + idx0]        = make_float2(pn0x, pn0y);
    o2[TOT2 + ND2 + idx0]  = make_float2(pn1x, pn1y);
}

extern "C" void kernel_launch(void* const* d_in, const int* in_sizes, int n_in,
                              void* d_out, int out_size) {
    const float* q   = (const float*)d_in[0];   // node_q  (B,N,D) f32
    const float* p   = (const float*)d_in[1];   // node_p  (B,N,D) f32
    const float* obs = (const float*)d_in[2];   // observations (B,D) f32
    const float* kg  = (const float*)d_in[3];   // kalman_gain (2D,) f32
    const int2*  edg = (const int2*)d_in[4];    // edges (E,2) i32
    float* out = (float*)d_out;

    bucket_kernel<<<(E + 255) / 256, 256>>>(edg);
    node_kernel<<<(N * 32 + 255) / 256, 256>>>(q, p, obs, kg, out);
}